// round 4
// baseline (speedup 1.0000x reference)
#include <cuda_runtime.h>
#include <cuda_bf16.h>
#include <cstdint>

// ============================================================================
// LogMM: out[16384,1024] = log( x[16384,1024] @ matrix[1024,1024] )
// (reference's big/small branches sum exactly to log(max(y,tiny)))
//
// R4: FP8 e4m3 mma.sync.m16n8k32 (baseline ISA, 2x bf16 rate).
//   1) cvt_kernel: fused  x fp32->e4m3  AND  matrix[K,N] fp32 -> Bt[N,K] e4m3
//   2) gemm: 128x128 tile, K-chunk=128 fp8 (128B rows), 3-stage cp.async,
//            2 CTAs/SM, fused __logf epilogue.
// Error: e4m3 noise averages over K=1024 positive terms -> rel_err ~2e-4.
// ============================================================================

#define M_TOTAL 16384
#define N_TOTAL 1024
#define K_TOTAL 1024
#define TILE_M 128
#define TILE_N 128
#define BK 128                   // fp8 elements per K-chunk (128 B per row)
#define NCHUNK (K_TOTAL / BK)    // 8
#define NSTAGE 3

// SMEM: [0..1024) pad, then 3 stages of (A tile 16KB + B tile 16KB)
static constexpr int SMEM_TILES = 1024;
static constexpr int TILE_BYTES = TILE_M * 128;     // 16384
static constexpr int BUF_STRIDE = 2 * TILE_BYTES;   // 32768
static constexpr int SMEM_TOTAL = SMEM_TILES + NSTAGE * BUF_STRIDE;  // 99328

// Scratch fp8 buffers (device globals: allocation-free)
__device__ __align__(256) uint8_t g_xb[(size_t)M_TOTAL * K_TOTAL];
__device__ __align__(256) uint8_t g_bt[(size_t)N_TOTAL * K_TOTAL];

// ---------------------------------------------------------------------------
// Helpers
// ---------------------------------------------------------------------------
__device__ __forceinline__ uint32_t smem_u32(const void* p) {
    uint32_t a;
    asm("{ .reg .u64 t; cvta.to.shared.u64 t, %1; cvt.u32.u64 %0, t; }" : "=r"(a) : "l"(p));
    return a;
}
__device__ __forceinline__ uint32_t sw128(uint32_t off) {
    return off ^ ((off >> 3) & 0x70);
}
__device__ __forceinline__ void cp_async16(uint32_t smem_addr, const void* gptr) {
    asm volatile("cp.async.cg.shared.global [%0], [%1], 16;"
                 :: "r"(smem_addr), "l"(gptr) : "memory");
}
#define CP_COMMIT() asm volatile("cp.async.commit_group;" ::: "memory")
#define CP_WAIT(n)  asm volatile("cp.async.wait_group %0;" :: "n"(n) : "memory")

__device__ __forceinline__ void ldsm_x4(uint32_t* r, uint32_t addr) {
    asm volatile("ldmatrix.sync.aligned.m8n8.x4.shared.b16 {%0, %1, %2, %3}, [%4];"
                 : "=r"(r[0]), "=r"(r[1]), "=r"(r[2]), "=r"(r[3]) : "r"(addr));
}
// FP8 e4m3 MMA: D[16x8] += A[16x32] * B[32x8], fp32 accum
__device__ __forceinline__ void mma16832(float* c, const uint32_t* a, const uint32_t* b) {
    asm volatile("mma.sync.aligned.m16n8k32.row.col.f32.e4m3.e4m3.f32 "
                 "{%0, %1, %2, %3}, {%4, %5, %6, %7}, {%8, %9}, {%0, %1, %2, %3};"
                 : "+f"(c[0]), "+f"(c[1]), "+f"(c[2]), "+f"(c[3])
                 : "r"(a[0]), "r"(a[1]), "r"(a[2]), "r"(a[3]), "r"(b[0]), "r"(b[1]));
}
// pack two floats into e4m3x2 (lo in byte0, hi in byte1)
__device__ __forceinline__ uint16_t pack_e4m3x2(float lo, float hi) {
    uint16_t r;
    asm("cvt.rn.satfinite.e4m3x2.f32 %0, %1, %2;" : "=h"(r) : "f"(hi), "f"(lo));
    return r;
}

// ---------------------------------------------------------------------------
// Fused conversion kernel:
//   blocks [0, 4096):        x fp32 -> g_xb e4m3 (16 elems/thread)
//   blocks [4096, 4096+1024): matrix[K,N] -> g_bt[N,K] e4m3 (32x32 tiles)
// ---------------------------------------------------------------------------
#define CVT_X_BLOCKS (M_TOTAL * K_TOTAL / (256 * 16))  // 4096
#define CVT_T_BLOCKS ((K_TOTAL / 32) * (N_TOTAL / 32)) // 1024

__global__ void __launch_bounds__(256)
cvt_kernel(const float* __restrict__ x, const float* __restrict__ m) {
    int tid = threadIdx.x;
    if (blockIdx.x < CVT_X_BLOCKS) {
        size_t i = ((size_t)blockIdx.x * 256 + tid) * 16;
        uint32_t o[4];
#pragma unroll
        for (int q = 0; q < 4; q++) {
            float4 a = *reinterpret_cast<const float4*>(x + i + q * 4);
            uint16_t p0 = pack_e4m3x2(a.x, a.y);
            uint16_t p1 = pack_e4m3x2(a.z, a.w);
            o[q] = (uint32_t)p0 | ((uint32_t)p1 << 16);
        }
        *reinterpret_cast<uint4*>(g_xb + i) =
            make_uint4(o[0], o[1], o[2], o[3]);
    } else {
        __shared__ float tile[32][33];
        int t = blockIdx.x - CVT_X_BLOCKS;
        int bn = (t & 31) * 32;          // n block
        int bk = (t >> 5) * 32;          // k block
        int lane = tid & 31;
        int rr = tid >> 5;               // 0..7
#pragma unroll
        for (int i = 0; i < 4; i++) {
            int row = i * 8 + rr;        // k within tile
            tile[row][lane] = m[(size_t)(bk + row) * N_TOTAL + bn + lane];
        }
        __syncthreads();
#pragma unroll
        for (int i = 0; i < 4; i++) {
            int row = i * 8 + rr;        // n within tile
            uint16_t p = pack_e4m3x2(tile[lane][row], 0.0f);
            g_bt[(size_t)(bn + row) * K_TOTAL + bk + lane] = (uint8_t)(p & 0xFF);
        }
    }
}

// ---------------------------------------------------------------------------
// GEMM + log kernel
// ---------------------------------------------------------------------------
__device__ __forceinline__ void load_tiles_async(uint32_t smem_base, int buf, int kc,
                                                 int m0, int n0, int tid) {
    const uint8_t* Ag = g_xb + (size_t)m0 * K_TOTAL + kc * BK;
    const uint8_t* Bg = g_bt + (size_t)n0 * K_TOTAL + kc * BK;
    uint32_t Abase = smem_base + SMEM_TILES + buf * BUF_STRIDE;
    uint32_t Bbase = Abase + TILE_BYTES;
#pragma unroll
    for (int i = 0; i < 4; i++) {
        int cc = i * 256 + tid;           // 1024 16B-chunks per tile
        int row = cc >> 3;                // 0..127
        int c16 = cc & 7;                 // 16B chunk within 128B row
        uint32_t sw = sw128((uint32_t)(row * 128 + c16 * 16));
        cp_async16(Abase + sw, Ag + (size_t)row * K_TOTAL + c16 * 16);
        cp_async16(Bbase + sw, Bg + (size_t)row * K_TOTAL + c16 * 16);
    }
}

__global__ void __launch_bounds__(256, 2)
logmm_gemm_kernel(float* __restrict__ out) {
    extern __shared__ char smem[];
    uint32_t sb = smem_u32(smem);
    int tid = threadIdx.x;
    int wid = tid >> 5;
    int lid = tid & 31;
    int n0 = blockIdx.x * TILE_N;
    int m0 = blockIdx.y * TILE_M;

    // 8 warps: warp_m in {0,1} (64 rows), warp_n in {0..3} (32 cols)
    int warp_m = wid >> 2;
    int warp_n = wid & 3;

    float acc[4][4][4];
#pragma unroll
    for (int mf = 0; mf < 4; mf++)
#pragma unroll
        for (int nf = 0; nf < 4; nf++)
#pragma unroll
            for (int i = 0; i < 4; i++) acc[mf][nf][i] = 0.0f;

    // Prologue: fill 2 of 3 stages
    load_tiles_async(sb, 0, 0, m0, n0, tid);
    CP_COMMIT();
    load_tiles_async(sb, 1, 1, m0, n0, tid);
    CP_COMMIT();

    // Precompute per-lane ldmatrix address components.
    // A (row-major, m16n8k32): matrices (rows_lo,klo),(rows_hi,klo),(rows_lo,khi),(rows_hi,khi)
    int a_row_l = (lid & 7) + ((lid >> 3) & 1) * 8;     // row within 16-row frag
    int a_kb_l  = ((lid >> 4) & 1) * 16;                // 0 or 16 bytes (k half)
    // B (Bt row-major over n, k contiguous): matrices (n_lo,klo),(n_lo,khi),(n_hi,klo),(n_hi,khi)
    int b_row_l = (lid & 7) + ((lid >> 4) & 1) * 8;     // n within 16-col group
    int b_kb_l  = ((lid >> 3) & 1) * 16;

    for (int c = 0; c < NCHUNK; c++) {
        if (c == NCHUNK - 1) { CP_WAIT(0); } else { CP_WAIT(1); }
        __syncthreads();

        if (c + 2 < NCHUNK) {
            load_tiles_async(sb, (c + 2) % NSTAGE, c + 2, m0, n0, tid);
            CP_COMMIT();
        }

        uint32_t Ab = sb + SMEM_TILES + (c % NSTAGE) * BUF_STRIDE;
        uint32_t Bb = Ab + TILE_BYTES;
#pragma unroll
        for (int ks = 0; ks < 4; ks++) {            // 4 x k32 per 128-fp8 chunk
            uint32_t a[4][4], b[2][4];
#pragma unroll
            for (int mf = 0; mf < 4; mf++) {
                int row = warp_m * 64 + mf * 16 + a_row_l;
                uint32_t off = (uint32_t)(row * 128 + ks * 32 + a_kb_l);
                ldsm_x4(a[mf], Ab + sw128(off));
            }
#pragma unroll
            for (int p = 0; p < 2; p++) {
                int row = warp_n * 32 + p * 16 + b_row_l;
                uint32_t off = (uint32_t)(row * 128 + ks * 32 + b_kb_l);
                ldsm_x4(b[p], Bb + sw128(off));
            }
#pragma unroll
            for (int mf = 0; mf < 4; mf++)
#pragma unroll
                for (int nf = 0; nf < 4; nf++)
                    mma16832(acc[mf][nf], a[mf], b[nf >> 1] + (nf & 1) * 2);
        }
    }

    // Epilogue: log + store. Frag: c0,c1 at row lid/4, cols (lid%4)*2,+1;
    // c2,c3 at row lid/4 + 8.
#pragma unroll
    for (int mf = 0; mf < 4; mf++) {
#pragma unroll
        for (int nf = 0; nf < 4; nf++) {
            int row0 = m0 + warp_m * 64 + mf * 16 + (lid >> 2);
            int col = n0 + warp_n * 32 + nf * 8 + (lid & 3) * 2;
            float2 v0, v1;
            v0.x = __logf(fmaxf(acc[mf][nf][0], 1.17549435e-38f));
            v0.y = __logf(fmaxf(acc[mf][nf][1], 1.17549435e-38f));
            v1.x = __logf(fmaxf(acc[mf][nf][2], 1.17549435e-38f));
            v1.y = __logf(fmaxf(acc[mf][nf][3], 1.17549435e-38f));
            *reinterpret_cast<float2*>(out + (size_t)row0 * N_TOTAL + col) = v0;
            *reinterpret_cast<float2*>(out + (size_t)(row0 + 8) * N_TOTAL + col) = v1;
        }
    }
}

// ---------------------------------------------------------------------------
// Launch
// ---------------------------------------------------------------------------
extern "C" void kernel_launch(void* const* d_in, const int* in_sizes, int n_in,
                              void* d_out, int out_size) {
    const float* x = (const float*)d_in[0];
    const float* mat = (const float*)d_in[1];
    if (n_in >= 2 && in_sizes[0] == N_TOTAL * K_TOTAL && in_sizes[1] == M_TOTAL * K_TOTAL) {
        const float* t = x; x = mat; mat = t;
    }
    float* out = (float*)d_out;

    cudaFuncSetAttribute(logmm_gemm_kernel,
                         cudaFuncAttributeMaxDynamicSharedMemorySize, SMEM_TOTAL);

    cvt_kernel<<<CVT_X_BLOCKS + CVT_T_BLOCKS, 256>>>(x, mat);
    dim3 grid(N_TOTAL / TILE_N, M_TOTAL / TILE_M);  // (8, 128)
    logmm_gemm_kernel<<<grid, 256, SMEM_TOTAL>>>(out);
}

// round 5
// speedup vs baseline: 1.1794x; 1.1794x over previous
#include <cuda_runtime.h>
#include <cuda_bf16.h>
#include <cstdint>

// ============================================================================
// LogMM: out[16384,1024] = log( x[16384,1024] @ matrix[1024,1024] )
// (reference's big/small branches sum exactly to log(max(y,tiny)))
//
// R5: bf16 mma.sync (FP8 reverted: mma.sync e4m3 has SAME MAC rate as bf16
// on this target, measured). Persistent-CTA GEMM: grid=296 (2 CTAs/SM), each
// CTA streams chunks across ALL its tiles through one 3-stage cp.async ring,
// so the pipeline never drains at tile boundaries and the log epilogue is
// covered by the next tile's loads.
// ============================================================================

#define M_TOTAL 16384
#define N_TOTAL 1024
#define K_TOTAL 1024
#define TILE_M 128
#define TILE_N 128
#define BK 64                    // bf16 per K-chunk (128 B per row)
#define NCHUNK (K_TOTAL / BK)    // 16
#define NSTAGE 3
#define NTILES ((M_TOTAL / TILE_M) * (N_TOTAL / TILE_N))  // 1024
#define GRID_GEMM 296            // 2 CTAs/SM x 148 SMs

static constexpr int SMEM_TILES = 1024;
static constexpr int TILE_BYTES = TILE_M * 128;     // 16384
static constexpr int BUF_STRIDE = 2 * TILE_BYTES;   // 32768
static constexpr int SMEM_TOTAL = SMEM_TILES + NSTAGE * BUF_STRIDE;  // 99328

// Scratch bf16 buffers (device globals: allocation-free)
__device__ __align__(256) __nv_bfloat16 g_xb[(size_t)M_TOTAL * K_TOTAL];
__device__ __align__(256) __nv_bfloat16 g_bt[(size_t)N_TOTAL * K_TOTAL];

// ---------------------------------------------------------------------------
// Helpers
// ---------------------------------------------------------------------------
__device__ __forceinline__ uint32_t smem_u32(const void* p) {
    uint32_t a;
    asm("{ .reg .u64 t; cvta.to.shared.u64 t, %1; cvt.u32.u64 %0, t; }" : "=r"(a) : "l"(p));
    return a;
}
__device__ __forceinline__ uint32_t sw128(uint32_t off) {
    return off ^ ((off >> 3) & 0x70);
}
__device__ __forceinline__ void cp_async16(uint32_t smem_addr, const void* gptr) {
    asm volatile("cp.async.cg.shared.global [%0], [%1], 16;"
                 :: "r"(smem_addr), "l"(gptr) : "memory");
}
#define CP_COMMIT() asm volatile("cp.async.commit_group;" ::: "memory")
#define CP_WAIT(n)  asm volatile("cp.async.wait_group %0;" :: "n"(n) : "memory")

__device__ __forceinline__ void ldsm_x4(uint32_t* r, uint32_t addr) {
    asm volatile("ldmatrix.sync.aligned.m8n8.x4.shared.b16 {%0, %1, %2, %3}, [%4];"
                 : "=r"(r[0]), "=r"(r[1]), "=r"(r[2]), "=r"(r[3]) : "r"(addr));
}
__device__ __forceinline__ void mma16816(float* c, const uint32_t* a, const uint32_t* b) {
    asm volatile("mma.sync.aligned.m16n8k16.row.col.f32.bf16.bf16.f32 "
                 "{%0, %1, %2, %3}, {%4, %5, %6, %7}, {%8, %9}, {%0, %1, %2, %3};"
                 : "+f"(c[0]), "+f"(c[1]), "+f"(c[2]), "+f"(c[3])
                 : "r"(a[0]), "r"(a[1]), "r"(a[2]), "r"(a[3]), "r"(b[0]), "r"(b[1]));
}
__device__ __forceinline__ uint32_t pack_bf16x2(float a, float b) {
    __nv_bfloat162 h = __floats2bfloat162_rn(a, b);
    return *reinterpret_cast<uint32_t*>(&h);
}

// ---------------------------------------------------------------------------
// Fused conversion kernel:
//   blocks [0, 8192):         x fp32 -> g_xb bf16 (8 elems/thread)
//   blocks [8192, 8192+1024): matrix[K,N] -> g_bt[N,K] bf16 (32x32 tiles)
// ---------------------------------------------------------------------------
#define CVT_X_BLOCKS (M_TOTAL * K_TOTAL / (256 * 8))   // 8192
#define CVT_T_BLOCKS ((K_TOTAL / 32) * (N_TOTAL / 32)) // 1024

__global__ void __launch_bounds__(256)
cvt_kernel(const float* __restrict__ x, const float* __restrict__ m) {
    int tid = threadIdx.x;
    if (blockIdx.x < CVT_X_BLOCKS) {
        size_t i = ((size_t)blockIdx.x * 256 + tid) * 8;
        float4 a = *reinterpret_cast<const float4*>(x + i);
        float4 b = *reinterpret_cast<const float4*>(x + i + 4);
        uint4 o;
        o.x = pack_bf16x2(a.x, a.y);
        o.y = pack_bf16x2(a.z, a.w);
        o.z = pack_bf16x2(b.x, b.y);
        o.w = pack_bf16x2(b.z, b.w);
        *reinterpret_cast<uint4*>(g_xb + i) = o;
    } else {
        __shared__ float tile[32][33];
        int t = blockIdx.x - CVT_X_BLOCKS;
        int bn = (t & 31) * 32;          // n block
        int bk = (t >> 5) * 32;          // k block
        int lane = tid & 31;
        int rr = tid >> 5;               // 0..7
#pragma unroll
        for (int i = 0; i < 4; i++) {
            int row = i * 8 + rr;        // k within tile
            tile[row][lane] = m[(size_t)(bk + row) * N_TOTAL + bn + lane];
        }
        __syncthreads();
#pragma unroll
        for (int i = 0; i < 4; i++) {
            int row = i * 8 + rr;        // n within tile
            g_bt[(size_t)(bn + row) * K_TOTAL + bk + lane] =
                __float2bfloat16_rn(tile[lane][row]);
        }
    }
}

// ---------------------------------------------------------------------------
// GEMM + log kernel (persistent, cross-tile pipelined)
// ---------------------------------------------------------------------------
// Issue cp.asyncs for global chunk g (tile = first + (g>>4)*GRID, kc = g&15)
__device__ __forceinline__ void issue_chunk(uint32_t smem_base, int g, int first, int tid) {
    int t = first + (g >> 4) * GRID_GEMM;
    int kc = g & (NCHUNK - 1);
    int m0 = (t >> 3) * TILE_M;
    int n0 = (t & 7) * TILE_N;
    const uint4* Ag = reinterpret_cast<const uint4*>(g_xb + (size_t)m0 * K_TOTAL + kc * BK);
    const uint4* Bg = reinterpret_cast<const uint4*>(g_bt + (size_t)n0 * K_TOTAL + kc * BK);
    uint32_t Abase = smem_base + SMEM_TILES + (g % NSTAGE) * BUF_STRIDE;
    uint32_t Bbase = Abase + TILE_BYTES;
#pragma unroll
    for (int i = 0; i < 4; i++) {
        int cc = i * 256 + tid;           // 1024 16B-chunks per tile
        int row = cc >> 3;                // 0..127
        int c16 = cc & 7;                 // 16B chunk within 128B row
        uint32_t sw = sw128((uint32_t)(row * 128 + c16 * 16));
        cp_async16(Abase + sw, Ag + (size_t)row * (K_TOTAL / 8) + c16);
        cp_async16(Bbase + sw, Bg + (size_t)row * (K_TOTAL / 8) + c16);
    }
    CP_COMMIT();
}

__global__ void __launch_bounds__(256, 2)
logmm_gemm_kernel(float* __restrict__ out) {
    extern __shared__ char smem[];
    uint32_t sb = smem_u32(smem);
    int tid = threadIdx.x;
    int wid = tid >> 5;
    int lid = tid & 31;

    // 8 warps: warp_m in {0,1} (64 rows), warp_n in {0..3} (32 cols)
    int warp_m = wid >> 2;
    int warp_n = wid & 3;

    int first = blockIdx.x;
    int my_tiles = (NTILES - 1 - first) / GRID_GEMM + 1;  // 3 or 4
    int G = my_tiles * NCHUNK;

    float acc[4][4][4];
#pragma unroll
    for (int mf = 0; mf < 4; mf++)
#pragma unroll
        for (int nf = 0; nf < 4; nf++)
#pragma unroll
            for (int i = 0; i < 4; i++) acc[mf][nf][i] = 0.0f;

    // Prologue: fill 2 of 3 stages
    issue_chunk(sb, 0, first, tid);
    issue_chunk(sb, 1, first, tid);

    for (int g = 0; g < G; g++) {
        if (g == G - 1) { CP_WAIT(0); } else { CP_WAIT(1); }
        __syncthreads();

        // Prefetch chunk g+2 (may belong to the NEXT tile -> no drain)
        if (g + 2 < G) issue_chunk(sb, g + 2, first, tid);

        uint32_t Ab = sb + SMEM_TILES + (g % NSTAGE) * BUF_STRIDE;
        uint32_t Bb = Ab + TILE_BYTES;
#pragma unroll
        for (int ks = 0; ks < 4; ks++) {
            uint32_t a[4][4], b[2][4];
#pragma unroll
            for (int mf = 0; mf < 4; mf++) {
                int row = warp_m * 64 + mf * 16 + (lid & 15);
                uint32_t off = (uint32_t)(row * 128 + ks * 32 + ((lid >> 4) << 4));
                ldsm_x4(a[mf], Ab + sw128(off));
            }
#pragma unroll
            for (int p = 0; p < 2; p++) {
                int row = warp_n * 32 + p * 16 + (lid & 7) + ((lid >> 4) << 3);
                uint32_t off = (uint32_t)(row * 128 + ks * 32 + (((lid >> 3) & 1) << 4));
                ldsm_x4(b[p], Bb + sw128(off));
            }
#pragma unroll
            for (int mf = 0; mf < 4; mf++)
#pragma unroll
                for (int nf = 0; nf < 4; nf++)
                    mma16816(acc[mf][nf], a[mf], b[nf >> 1] + (nf & 1) * 2);
        }

        // Tile finished? Epilogue overlapped with in-flight next-tile loads.
        if ((g & (NCHUNK - 1)) == NCHUNK - 1) {
            int t = first + (g >> 4) * GRID_GEMM;
            int m0 = (t >> 3) * TILE_M;
            int n0 = (t & 7) * TILE_N;
#pragma unroll
            for (int mf = 0; mf < 4; mf++) {
#pragma unroll
                for (int nf = 0; nf < 4; nf++) {
                    int row0 = m0 + warp_m * 64 + mf * 16 + (lid >> 2);
                    int col = n0 + warp_n * 32 + nf * 8 + (lid & 3) * 2;
                    float2 v0, v1;
                    v0.x = __logf(fmaxf(acc[mf][nf][0], 1.17549435e-38f));
                    v0.y = __logf(fmaxf(acc[mf][nf][1], 1.17549435e-38f));
                    v1.x = __logf(fmaxf(acc[mf][nf][2], 1.17549435e-38f));
                    v1.y = __logf(fmaxf(acc[mf][nf][3], 1.17549435e-38f));
                    *reinterpret_cast<float2*>(out + (size_t)row0 * N_TOTAL + col) = v0;
                    *reinterpret_cast<float2*>(out + (size_t)(row0 + 8) * N_TOTAL + col) = v1;
                    acc[mf][nf][0] = 0.0f;
                    acc[mf][nf][1] = 0.0f;
                    acc[mf][nf][2] = 0.0f;
                    acc[mf][nf][3] = 0.0f;
                }
            }
        }
    }
}

// ---------------------------------------------------------------------------
// Launch
// ---------------------------------------------------------------------------
extern "C" void kernel_launch(void* const* d_in, const int* in_sizes, int n_in,
                              void* d_out, int out_size) {
    const float* x = (const float*)d_in[0];
    const float* mat = (const float*)d_in[1];
    if (n_in >= 2 && in_sizes[0] == N_TOTAL * K_TOTAL && in_sizes[1] == M_TOTAL * K_TOTAL) {
        const float* t = x; x = mat; mat = t;
    }
    float* out = (float*)d_out;

    cudaFuncSetAttribute(logmm_gemm_kernel,
                         cudaFuncAttributeMaxDynamicSharedMemorySize, SMEM_TOTAL);

    cvt_kernel<<<CVT_X_BLOCKS + CVT_T_BLOCKS, 256>>>(x, mat);
    logmm_gemm_kernel<<<GRID_GEMM, 256, SMEM_TOTAL>>>(out);
}